// round 14
// baseline (speedup 1.0000x reference)
#include <cuda_runtime.h>
#include <math.h>

// ---------------- problem constants ----------------
#define BB   64
#define SS   250
#define CLL  16
#define CVV  100
#define CHH  50
#define FDD  5
#define WDD  300
#define CDD  300
#define HH   100
#define G4   400      // 4*H
#define INN  355      // WD + CH + FD
#define KP   360      // padded K for GEMM
#define N2   800      // both directions' gates
#define N2P  896      // padded N for GEMM loads
#define NS   (BB*SS)  // 16000
#define TT   22
#define START_TAG 20
#define STOP_TAG  21

typedef unsigned long long ull;

// ---------------- resolved input pointers ----------------
__device__ const int   *P_word, *P_feat, *P_len, *P_char, *P_rec;
__device__ const float *P_cemb, *P_wemb, *P_femb, *P_cw, *P_cb;
__device__ const float *P_wihf, *P_whhf, *P_bf, *P_wihb, *P_whhb, *P_bb;
__device__ const float *P_pw, *P_pb, *P_tr;

// ---------------- scratch ----------------
__device__ float g_proj[CVV*3*CHH];
__device__ float g_charmax[NS*CHH];
__device__ float g_W[KP*N2P];
__device__ float g_pre[NS*N2];
__device__ float g_lstm[NS*(2*HH)];
__device__ float g_feats[NS*TT];

// MUFU-based activations (R11 formulas; rel_err 0.0)
__device__ __forceinline__ float sigf(float x) {
    return __fdividef(1.0f, 1.0f + __expf(-x));
}
__device__ __forceinline__ float tanhf_fast(float x) {
    float e = __expf(2.0f * x);
    return 1.0f - __fdividef(2.0f, e + 1.0f);
}

// ---------------- packed fp32x2 helpers ----------------
__device__ __forceinline__ ull ffma2(ull a, ull b, ull c) {
    ull d;
    asm("fma.rn.f32x2 %0, %1, %2, %3;" : "=l"(d) : "l"(a), "l"(b), "l"(c));
    return d;
}
__device__ __forceinline__ ull faddx2(ull a, ull b) {
    ull d;
    asm("add.rn.f32x2 %0, %1, %2;" : "=l"(d) : "l"(a), "l"(b));
    return d;
}
__device__ __forceinline__ ull fdup(float a) {
    ull r;
    asm("mov.b64 %0, {%1, %1};" : "=l"(r) : "f"(a));
    return r;
}
__device__ __forceinline__ ull fpk(float a, float b) {
    ull r;
    asm("mov.b64 %0, {%1, %2};" : "=l"(r) : "f"(a), "f"(b));
    return r;
}
__device__ __forceinline__ float2 fupk(ull v) {
    float2 f;
    asm("mov.b64 {%0, %1}, %2;" : "=f"(f.x), "=f"(f.y) : "l"(v));
    return f;
}

// ---------------- host-resolved fixed pointers ----------------
struct FixedPtrs {
    const float *wemb, *cemb, *cw, *pw, *pb, *tr;
    const float *wihf, *wihb, *whhf, *whhb, *bf, *bb;
    const int   *chr, *len;
    const int   *c16[5]; int n16;
    const float *c50[2]; int n50;
};

// ---------------- K0: fused resolve + coalesced buildW transpose + charproj ----------------
#define GT 28   // g2 tiles (28*32 = 896 = N2P)
#define KT 12   // k  tiles (12*32 = 384 >= KP)
__global__ __launch_bounds__(512, 2)
void k_init(FixedPtrs fp) {
    int bid = blockIdx.x;
    int tid = threadIdx.x;
    if (bid == 0) {
        int w = tid >> 5, lane = tid & 31;
        if (w < fp.n16 && w < 5) {
            const int* v = fp.c16[w];
            bool isrec = true, ble1 = true;
            int mn = 0x7fffffff, mx = -0x7fffffff;
            #pragma unroll
            for (int k = lane; k < 256; k += 32) {
                int x = v[k];
                if (x != k) isrec = false;
                unsigned u = (unsigned)x;
                if (((u)&0xFFu) > 1u || ((u>>8)&0xFFu) > 1u ||
                    ((u>>16)&0xFFu) > 1u || ((u>>24)&0xFFu) > 1u) ble1 = false;
                mn = min(mn, x); mx = max(mx, x);
            }
            isrec = __all_sync(0xffffffffu, isrec);
            ble1  = __all_sync(0xffffffffu, ble1);
            #pragma unroll
            for (int off = 16; off; off >>= 1) {
                mn = min(mn, __shfl_xor_sync(0xffffffffu, mn, off));
                mx = max(mx, __shfl_xor_sync(0xffffffffu, mx, off));
            }
            if (lane == 0) {
                if (isrec)                    P_rec  = v;
                else if (ble1)                { /* mask: unused */ }
                else if (mn >= 0 && mx <= 9)  P_feat = v;
                else if (mn >= 1 && mx <= 16) { /* charlen: unused */ }
                else                          P_word = v;
            }
        } else if (w == 5) {
            for (int j = 0; j < fp.n50; j++) {
                const float* f = fp.c50[j];
                bool nz = false;
                for (int k = lane; k < 50; k += 32) nz |= (f[k] != 0.0f);
                bool anynz = __any_sync(0xffffffffu, nz);
                if (lane == 0) { if (anynz) P_femb = f; else P_cb = f; }
            }
        } else if (w == 6 && lane == 0) {
            P_wemb = fp.wemb; P_cemb = fp.cemb; P_cw = fp.cw;
            P_pw = fp.pw; P_pb = fp.pb; P_tr = fp.tr;
            P_wihf = fp.wihf; P_wihb = fp.wihb;
            P_whhf = fp.whhf; P_whhb = fp.whhb;
            P_bf = fp.bf; P_bb = fp.bb;
            P_char = fp.chr; P_len = fp.len;
        }
    } else if (bid <= GT*KT) {
        __shared__ float tile[32][33];
        int t  = bid - 1;
        int kt = t / GT;
        int gt = t % GT;
        int tx  = tid & 31;
        int ty0 = tid >> 5;
        #pragma unroll
        for (int h2 = 0; h2 < 2; h2++) {
            int ty = ty0 + h2*16;
            int g2 = gt*32 + ty;
            int k  = kt*32 + tx;
            float v = 0.f;
            if (k < INN && g2 < N2)
                v = (g2 < G4) ? fp.wihf[g2*INN + k] : fp.wihb[(g2-G4)*INN + k];
            tile[ty][tx] = v;
        }
        __syncthreads();
        #pragma unroll
        for (int h2 = 0; h2 < 2; h2++) {
            int r  = ty0 + h2*16;
            int k2 = kt*32 + r;
            int g2 = gt*32 + tx;
            if (k2 < KP)
                g_W[(size_t)k2*N2P + g2] = tile[tx][r];
        }
    } else {
        const float* char_emb = fp.cemb;
        const float* conv_w   = fp.cw;
        __shared__ float sce[CDD];
        int c = bid - (GT*KT + 1);
        for (int d = tid; d < CDD; d += blockDim.x)
            sce[d] = char_emb[c*CDD + d];
        __syncthreads();
        if (tid < 3*CHH) {
            int k = tid / CHH, o = tid % CHH;
            float acc = 0.f;
            #pragma unroll 4
            for (int d = 0; d < CDD; d++)
                acc += __ldg(conv_w + (o*CDD + d)*3 + k) * sce[d];
            g_proj[(c*3 + k)*CHH + o] = acc;
        }
    }
}

// ---------------- K1: char conv + max-pool ----------------
__global__ void k_charmax() {
    const int*   batch_char = P_char;
    const float* conv_b     = P_cb;
    __shared__ int chs[4][CLL];
    int t = threadIdx.x & 63;
    int ns = threadIdx.x >> 6;
    int n = blockIdx.x*4 + ns;
    if (t < CLL) chs[ns][t] = batch_char[n*CLL + t];
    __syncthreads();
    if (t < CHH) {
        float bo = conv_b[t];
        float best = -1e30f;
        #pragma unroll
        for (int p = 0; p < CLL; p++) {
            float v = bo;
            #pragma unroll
            for (int k = 0; k < 3; k++) {
                int q = p + k - 1;
                if (q >= 0 && q < CLL)
                    v += __ldg(&g_proj[(chs[ns][q]*3 + k)*CHH + t]);
            }
            best = fmaxf(best, v);
        }
        g_charmax[n*CHH + t] = best;
    }
}

// ---------------- K2: SGEMM, fused A-gather, double-buffered ----------------
#define BM 128
#define BN 128
#define BKK 8
#define NT (KP/BKK)   // 45
__global__ __launch_bounds__(256, 2)
void k_gemm() {
    const float* b_f  = P_bf;
    const float* b_b  = P_bb;
    const float* femb = P_femb;
    __shared__ __align__(16) float As[2][BKK][BM + 4];
    __shared__ __align__(16) float Bs[2][BKK][BN];
    __shared__ int sw[BM], sr[BM], sf[BM];
    int bm = blockIdx.x * BM;
    int bn = blockIdx.y * BN;
    int tid = threadIdx.x;
    int am = tid >> 1, ak = (tid & 1) * 4;
    int bk = tid >> 5, bn4 = (tid & 31) * 4;
    int tx = tid & 15, ty = tid >> 4;

    for (int i = tid; i < BM; i += 256) {
        int m = bm + i;
        sw[i] = P_word[m];
        sr[i] = P_rec[m];
        sf[i] = P_feat[m];
    }
    __syncthreads();
    int myr = sr[am], myf = sf[am];
    const float* wrow = P_wemb + (size_t)sw[am]*WDD;

    ull acc2[8][4];
    #pragma unroll
    for (int i = 0; i < 8; i++)
        #pragma unroll
        for (int j = 0; j < 4; j++) acc2[i][j] = 0ull;

    float4 a4, b4;
    #define GATHER(t) {                                                          \
        int k = (t)*BKK + ak;                                                    \
        if (k + 3 < WDD) {                                                       \
            a4 = *(const float4*)(wrow + k);                                     \
        } else {                                                                 \
            float vv[4];                                                         \
            _Pragma("unroll")                                                    \
            for (int c = 0; c < 4; c++) {                                        \
                int kk2 = k + c;                                                 \
                float x = 0.f;                                                   \
                if (kk2 < WDD)           x = __ldg(wrow + kk2);                  \
                else if (kk2 < WDD+CHH)  x = g_charmax[myr*CHH + kk2 - WDD];     \
                else if (kk2 < INN)      x = __ldg(femb + myf*FDD + (kk2 - WDD - CHH)); \
                vv[c] = x;                                                       \
            }                                                                    \
            a4 = make_float4(vv[0], vv[1], vv[2], vv[3]);                        \
        }                                                                        \
        b4 = *(const float4*)(g_W + (size_t)((t)*BKK + bk)*N2P + bn + bn4);      \
    }
    #define STORE(buf) {                                                         \
        As[buf][ak+0][am] = a4.x; As[buf][ak+1][am] = a4.y;                      \
        As[buf][ak+2][am] = a4.z; As[buf][ak+3][am] = a4.w;                      \
        *(float4*)&Bs[buf][bk][bn4] = b4;                                        \
    }

    GATHER(0); STORE(0);
    __syncthreads();
    for (int t = 0; t < NT; t++) {
        int cur = t & 1;
        if (t + 1 < NT) GATHER(t + 1);
        #pragma unroll
        for (int kk = 0; kk < BKK; kk++) {
            float4 a0 = *(const float4*)&As[cur][kk][ty*8];
            float4 a1 = *(const float4*)&As[cur][kk][ty*8 + 4];
            ulonglong2 bL = *(const ulonglong2*)&Bs[cur][kk][tx*4];
            ulonglong2 bH = *(const ulonglong2*)&Bs[cur][kk][64 + tx*4];
            ull br2[4];
            br2[0] = bL.x; br2[1] = bL.y; br2[2] = bH.x; br2[3] = bH.y;
            float ar[8];
            ar[0]=a0.x; ar[1]=a0.y; ar[2]=a0.z; ar[3]=a0.w;
            ar[4]=a1.x; ar[5]=a1.y; ar[6]=a1.z; ar[7]=a1.w;
            #pragma unroll
            for (int i = 0; i < 8; i++) {
                ull a2 = fdup(ar[i]);
                #pragma unroll
                for (int j2 = 0; j2 < 4; j2++)
                    acc2[i][j2] = ffma2(a2, br2[j2], acc2[i][j2]);
            }
        }
        if (t + 1 < NT) STORE(cur ^ 1);
        __syncthreads();
    }

    #pragma unroll
    for (int i = 0; i < 8; i++) {
        int m = bm + ty*8 + i;
        #pragma unroll
        for (int j2 = 0; j2 < 4; j2++) {
            float2 v = fupk(acc2[i][j2]);
            int col = (j2 < 2) ? (tx*4 + 2*j2) : (64 + tx*4 + 2*(j2-2));
            int n0 = bn + col;
            if (n0 < N2) {
                float bias0 = (n0 < G4) ? __ldg(b_f + n0) : __ldg(b_b + n0 - G4);
                g_pre[(size_t)m*N2 + n0] = v.x + bias0;
            }
            int n1 = n0 + 1;
            if (n1 < N2) {
                float bias1 = (n1 < G4) ? __ldg(b_f + n1) : __ldg(b_b + n1 - G4);
                g_pre[(size_t)m*N2 + n1] = v.y + bias1;
            }
        }
    }
}

// ---------------- K3: LSTM recurrence — 2 batches/block sharing weights ----------------
// Block bx: dir = bx>>5, batch pair (2*(bx&31), 2*(bx&31)+1), same direction.
// Weights (100 regs) loaded ONCE, used for both batches. The two independent
// recurrence chains interleave between barriers, hiding each other's latency.
// Per-batch math verbatim R11 -> bit-identical results.
__global__ __launch_bounds__(416, 1)
void k_lstm() {
    int bx  = blockIdx.x;           // 0..63
    int dir = bx >> 5;
    int bp  = bx & 31;
    int b0  = bp*2, b1 = bp*2 + 1;
    const float* w = (dir == 0) ? P_whhf : P_whhb;
    int tid  = threadIdx.x;
    int lane = tid & 31;
    int q    = lane >> 3;
    int j    = (tid >> 5)*8 + (lane & 7);   // 0..103 (warp 12 partial)
    bool jok = (j < HH);

    __shared__ __align__(16) ull h_dup[2][2][104];  // [batch][buf][slot]

    ull wif[25], wgo[25];
    {
        int k0 = q*25;
        if (jok) {
            const float* wi = w + (size_t)j*HH        + k0;
            const float* wf = w + (size_t)(HH+j)*HH   + k0;
            const float* wg = w + (size_t)(2*HH+j)*HH + k0;
            const float* wo = w + (size_t)(3*HH+j)*HH + k0;
            #pragma unroll
            for (int t = 0; t < 25; t++) {
                wif[t] = fpk(__ldg(wi + t), __ldg(wf + t));
                wgo[t] = fpk(__ldg(wg + t), __ldg(wo + t));
            }
        } else {
            #pragma unroll
            for (int t = 0; t < 25; t++) { wif[t] = 0ull; wgo[t] = 0ull; }
        }
    }
    if (tid < 104) {
        h_dup[0][0][tid] = 0ull; h_dup[0][1][tid] = 0ull;
        h_dup[1][0][tid] = 0ull; h_dup[1][1][tid] = 0ull;
    }
    float c0 = 0.f, h0 = 0.f, c1 = 0.f, h1 = 0.f;
    int len0 = P_len[b0];
    int len1 = P_len[b1];
    int hidx = (j/25)*26 + (j%25);
    __syncthreads();

    const float* prebA = g_pre + (size_t)(b0*SS)*N2 + dir*G4 + q*HH + j;
    const float* prebB = g_pre + (size_t)(b1*SS)*N2 + dir*G4 + q*HH + j;
    int s0 = dir ? (SS-1) : 0;
    int ds = dir ? -1 : 1;

    #define CLAMPS(x) ((x) < 0 ? 0 : ((x) > SS-1 ? SS-1 : (x)))
    float pA0 = jok ? __ldg(prebA + (size_t)CLAMPS(s0)*N2)      : 0.f;
    float pA1 = jok ? __ldg(prebA + (size_t)CLAMPS(s0+ds)*N2)   : 0.f;
    float pB0 = jok ? __ldg(prebB + (size_t)CLAMPS(s0)*N2)      : 0.f;
    float pB1 = jok ? __ldg(prebB + (size_t)CLAMPS(s0+ds)*N2)   : 0.f;

    int s = s0;
    for (int it = 0; it < SS; it++, s += ds) {
        int s2 = CLAMPS(s + 2*ds);
        float pAn = jok ? __ldg(prebA + (size_t)s2*N2) : 0.f;
        float pBn = jok ? __ldg(prebB + (size_t)s2*N2) : 0.f;

        int cur = it & 1;
        ull aifA = (q == 0) ? fpk(pA0, 0.f) : (q == 1) ? fpk(0.f, pA0) : 0ull;
        ull agoA = (q == 2) ? fpk(pA0, 0.f) : (q == 3) ? fpk(0.f, pA0) : 0ull;
        ull aifB = (q == 0) ? fpk(pB0, 0.f) : (q == 1) ? fpk(0.f, pB0) : 0ull;
        ull agoB = (q == 2) ? fpk(pB0, 0.f) : (q == 3) ? fpk(0.f, pB0) : 0ull;
        const ulonglong2* hdA = (const ulonglong2*)&h_dup[0][cur][q*26];
        const ulonglong2* hdB = (const ulonglong2*)&h_dup[1][cur][q*26];
        #pragma unroll
        for (int t = 0; t < 12; t++) {
            ulonglong2 hpA = hdA[t];
            ulonglong2 hpB = hdB[t];
            aifA = ffma2(wif[2*t],   hpA.x, aifA);
            aifB = ffma2(wif[2*t],   hpB.x, aifB);
            agoA = ffma2(wgo[2*t],   hpA.x, agoA);
            agoB = ffma2(wgo[2*t],   hpB.x, agoB);
            aifA = ffma2(wif[2*t+1], hpA.y, aifA);
            aifB = ffma2(wif[2*t+1], hpB.y, aifB);
            agoA = ffma2(wgo[2*t+1], hpA.y, agoA);
            agoB = ffma2(wgo[2*t+1], hpB.y, agoB);
        }
        {
            ull hpA = h_dup[0][cur][q*26 + 24];
            ull hpB = h_dup[1][cur][q*26 + 24];
            aifA = ffma2(wif[24], hpA, aifA);
            aifB = ffma2(wif[24], hpB, aifB);
            agoA = ffma2(wgo[24], hpA, agoA);
            agoB = ffma2(wgo[24], hpB, agoB);
        }
        aifA = faddx2(aifA, __shfl_xor_sync(0xffffffffu, aifA, 8));
        aifB = faddx2(aifB, __shfl_xor_sync(0xffffffffu, aifB, 8));
        agoA = faddx2(agoA, __shfl_xor_sync(0xffffffffu, agoA, 8));
        agoB = faddx2(agoB, __shfl_xor_sync(0xffffffffu, agoB, 8));
        aifA = faddx2(aifA, __shfl_xor_sync(0xffffffffu, aifA, 16));
        aifB = faddx2(aifB, __shfl_xor_sync(0xffffffffu, aifB, 16));
        agoA = faddx2(agoA, __shfl_xor_sync(0xffffffffu, agoA, 16));
        agoB = faddx2(agoB, __shfl_xor_sync(0xffffffffu, agoB, 16));
        float2 sifA = fupk(aifA);
        float2 sgoA = fupk(agoA);
        float2 sifB = fupk(aifB);
        float2 sgoB = fupk(agoB);
        // two independent activation chains (interleaved by the scheduler)
        float cnA = sigf(sifA.y)*c0 + sigf(sifA.x)*tanhf_fast(sgoA.x);
        float cnB = sigf(sifB.y)*c1 + sigf(sifB.x)*tanhf_fast(sgoB.x);
        float hnA = sigf(sgoA.y)*tanhf_fast(cnA);
        float hnB = sigf(sgoB.y)*tanhf_fast(cnB);
        if (s < len0) { c0 = cnA; h0 = hnA; }
        if (s < len1) { c1 = cnB; h1 = hnB; }
        if (q == 0 && jok) {
            h_dup[0][cur ^ 1][hidx] = fdup(h0);
            h_dup[1][cur ^ 1][hidx] = fdup(h1);
            g_lstm[(size_t)(b0*SS + s)*(2*HH) + dir*HH + j] = h0;
            g_lstm[(size_t)(b1*SS + s)*(2*HH) + dir*HH + j] = h1;
        }
        __syncthreads();
        pA0 = pA1; pA1 = pAn;
        pB0 = pB1; pB1 = pBn;
    }
    #undef CLAMPS
}

// ---------------- K4: emission projection (4 accumulator chains) ----------------
__global__ void k_feats() {
    const float* proj_w = P_pw;
    const float* proj_b = P_pb;
    __shared__ float rows[8][2*HH];
    int wrp = threadIdx.x >> 5;
    int lane = threadIdx.x & 31;
    int n = blockIdx.x*8 + wrp;
    const float* src = g_lstm + (size_t)n*(2*HH);
    for (int k = lane; k < 2*HH; k += 32)
        rows[wrp][k] = src[k];
    __syncwarp();
    if (lane < TT) {
        float a0 = 0.f, a1 = 0.f, a2 = 0.f, a3 = 0.f;
        #pragma unroll 4
        for (int k = 0; k < 2*HH; k += 4) {
            a0 += rows[wrp][k+0] * __ldg(proj_w + (k+0)*TT + lane);
            a1 += rows[wrp][k+1] * __ldg(proj_w + (k+1)*TT + lane);
            a2 += rows[wrp][k+2] * __ldg(proj_w + (k+2)*TT + lane);
            a3 += rows[wrp][k+3] * __ldg(proj_w + (k+3)*TT + lane);
        }
        g_feats[(size_t)n*TT + lane] = __ldg(proj_b + lane) + ((a0 + a1) + (a2 + a3));
    }
}

// ---------------- K5: Viterbi — tree argmax ----------------
__device__ __forceinline__ void argmax22(const float* sc, float& bv, int& bi) {
    float v[22]; int ix[22];
    #pragma unroll
    for (int i = 0; i < 22; i++) { v[i] = sc[i]; ix[i] = i; }
    #pragma unroll
    for (int st = 16; st >= 1; st >>= 1) {
        #pragma unroll
        for (int i = 0; i < 22; i++) {
            if (i < st && i + st < 22) {
                bool r = v[i + st] > v[i];
                v[i]  = r ? v[i + st]  : v[i];
                ix[i] = r ? ix[i + st] : ix[i];
            }
        }
    }
    bv = v[0]; bi = ix[0];
}

__global__ void k_viterbi(float* __restrict__ out) {
    const float* trans = P_tr;
    const int*   lens  = P_len;
    int b = blockIdx.x;
    int j = threadIdx.x;
    __shared__ float tr[TT*TT];
    __shared__ float delta[TT];
    __shared__ unsigned char bp[(SS-1)*TT];
    for (int i = j; i < TT*TT; i += 32) tr[i] = trans[i];
    int len = lens[b];
    const float* fb = g_feats + (size_t)b*SS*TT;
    __syncwarp();
    if (j < TT) delta[j] = tr[START_TAG*TT + j] + __ldg(fb + j);
    __syncwarp();

    float fcur = (j < TT) ? __ldg(fb + TT + j) : 0.f;
    for (int t = 1; t < SS; t++) {
        float fnext = 0.f;
        if (j < TT && t < SS-1) fnext = __ldg(fb + (size_t)(t+1)*TT + j);
        float nd = 0.f; int nb = 0;
        if (j < TT) {
            float sc[TT];
            #pragma unroll
            for (int i = 0; i < TT; i++) sc[i] = delta[i] + tr[i*TT + j];
            float best; int bi;
            argmax22(sc, best, bi);
            if (t < len) { nd = best + fcur; nb = bi; }
            else         { nd = delta[j];    nb = j;  }
        }
        __syncwarp();
        if (j < TT) { delta[j] = nd; bp[(t-1)*TT + j] = (unsigned char)nb; }
        __syncwarp();
        fcur = fnext;
    }
    if (j == 0) {
        float sc[TT];
        #pragma unroll
        for (int i = 0; i < TT; i++) sc[i] = delta[i] + tr[i*TT + STOP_TAG];
        float best; int bi;
        argmax22(sc, best, bi);
        int tag = bi;
        out[b*SS + SS-1] = (float)tag;
        for (int s = SS-2; s >= 0; s--) {
            tag = bp[s*TT + tag];
            out[b*SS + s] = (float)tag;
        }
    }
}

// ---------------- launcher ----------------
extern "C" void kernel_launch(void* const* d_in, const int* in_sizes, int n_in,
                              void* d_out, int out_size) {
    FixedPtrs fp;
    fp.n16 = 0; fp.n50 = 0;
    int n142 = 0, n40k = 0, n400 = 0;
    for (int i = 0; i < n_in; i++) {
        int s = in_sizes[i];
        const void* p = d_in[i];
        if (s == 15000000)      fp.wemb = (const float*)p;
        else if (s == 256000)   fp.chr  = (const int*)p;
        else if (s == 64)       fp.len  = (const int*)p;
        else if (s == 30000)    fp.cemb = (const float*)p;
        else if (s == 45000)    fp.cw   = (const float*)p;
        else if (s == 4400)     fp.pw   = (const float*)p;
        else if (s == 22)       fp.pb   = (const float*)p;
        else if (s == 484)      fp.tr   = (const float*)p;
        else if (s == 142000) { if (n142++ == 0) fp.wihf = (const float*)p; else fp.wihb = (const float*)p; }
        else if (s == 40000)  { if (n40k++ == 0) fp.whhf = (const float*)p; else fp.whhb = (const float*)p; }
        else if (s == 400)    { if (n400++ == 0) fp.bf   = (const float*)p; else fp.bb   = (const float*)p; }
        else if (s == 50)     { if (fp.n50 < 2) fp.c50[fp.n50++] = (const float*)p; }
        else if (s == 16000)  { if (fp.n16 < 5) fp.c16[fp.n16++] = (const int*)p; }
    }

    k_init<<<1 + GT*KT + CVV, 512>>>(fp);    // launch 0
    k_charmax<<<NS/4, 256>>>();              // launch 1
    dim3 gg((NS + BM - 1)/BM, (N2P + BN - 1)/BN);
    k_gemm<<<gg, 256>>>();                   // launch 2
    k_lstm<<<64, 416>>>();                   // launch 3  <- ncu target (2 batches/block)
    k_feats<<<NS/8, 256>>>();                // launch 4
    k_viterbi<<<BB, 32>>>((float*)d_out);    // launch 5
}

// round 15
// speedup vs baseline: 1.2000x; 1.2000x over previous
#include <cuda_runtime.h>
#include <math.h>

// ---------------- problem constants ----------------
#define BB   64
#define SS   250
#define CLL  16
#define CVV  100
#define CHH  50
#define FDD  5
#define WDD  300
#define CDD  300
#define HH   100
#define G4   400      // 4*H
#define INN  355      // WD + CH + FD
#define KP   360      // padded K for GEMM
#define N2   800      // both directions' gates
#define N2P  896      // padded N for GEMM loads
#define NS   (BB*SS)  // 16000
#define TT   22
#define START_TAG 20
#define STOP_TAG  21

typedef unsigned long long ull;

// ---------------- resolved input pointers ----------------
__device__ const int   *P_word, *P_feat, *P_len, *P_char, *P_rec;
__device__ const float *P_cemb, *P_wemb, *P_femb, *P_cw, *P_cb;
__device__ const float *P_wihf, *P_whhf, *P_bf, *P_wihb, *P_whhb, *P_bb;
__device__ const float *P_pw, *P_pb, *P_tr;

// ---------------- scratch ----------------
__device__ float g_proj[CVV*3*CHH];
__device__ float g_charmax[NS*CHH];
__device__ float g_W[KP*N2P];
__device__ float g_pre[NS*N2];
__device__ float g_lstm[NS*(2*HH)];
__device__ float g_feats[NS*TT];

// MUFU-based activations (R11 formulas; rel_err 0.0)
__device__ __forceinline__ float sigf(float x) {
    return __fdividef(1.0f, 1.0f + __expf(-x));
}
__device__ __forceinline__ float tanhf_fast(float x) {
    float e = __expf(2.0f * x);
    return 1.0f - __fdividef(2.0f, e + 1.0f);
}

// ---------------- packed fp32x2 helpers ----------------
__device__ __forceinline__ ull ffma2(ull a, ull b, ull c) {
    ull d;
    asm("fma.rn.f32x2 %0, %1, %2, %3;" : "=l"(d) : "l"(a), "l"(b), "l"(c));
    return d;
}
__device__ __forceinline__ ull faddx2(ull a, ull b) {
    ull d;
    asm("add.rn.f32x2 %0, %1, %2;" : "=l"(d) : "l"(a), "l"(b));
    return d;
}
__device__ __forceinline__ ull fdup(float a) {
    ull r;
    asm("mov.b64 %0, {%1, %1};" : "=l"(r) : "f"(a));
    return r;
}
__device__ __forceinline__ ull fpk(float a, float b) {
    ull r;
    asm("mov.b64 %0, {%1, %2};" : "=l"(r) : "f"(a), "f"(b));
    return r;
}
__device__ __forceinline__ float2 fupk(ull v) {
    float2 f;
    asm("mov.b64 {%0, %1}, %2;" : "=f"(f.x), "=f"(f.y) : "l"(v));
    return f;
}

// ---------------- host-resolved fixed pointers ----------------
struct FixedPtrs {
    const float *wemb, *cemb, *cw, *pw, *pb, *tr;
    const float *wihf, *wihb, *whhf, *whhb, *bf, *bb;
    const int   *chr, *len;
    const int   *c16[5]; int n16;
    const float *c50[2]; int n50;
};

// ---------------- K0: fused resolve + coalesced buildW transpose + charproj ----------------
#define GT 28   // g2 tiles (28*32 = 896 = N2P)
#define KT 12   // k  tiles (12*32 = 384 >= KP)
__global__ __launch_bounds__(512, 2)
void k_init(FixedPtrs fp) {
    int bid = blockIdx.x;
    int tid = threadIdx.x;
    if (bid == 0) {
        int w = tid >> 5, lane = tid & 31;
        if (w < fp.n16 && w < 5) {
            const int* v = fp.c16[w];
            bool isrec = true, ble1 = true;
            int mn = 0x7fffffff, mx = -0x7fffffff;
            #pragma unroll
            for (int k = lane; k < 256; k += 32) {
                int x = v[k];
                if (x != k) isrec = false;
                unsigned u = (unsigned)x;
                if (((u)&0xFFu) > 1u || ((u>>8)&0xFFu) > 1u ||
                    ((u>>16)&0xFFu) > 1u || ((u>>24)&0xFFu) > 1u) ble1 = false;
                mn = min(mn, x); mx = max(mx, x);
            }
            isrec = __all_sync(0xffffffffu, isrec);
            ble1  = __all_sync(0xffffffffu, ble1);
            #pragma unroll
            for (int off = 16; off; off >>= 1) {
                mn = min(mn, __shfl_xor_sync(0xffffffffu, mn, off));
                mx = max(mx, __shfl_xor_sync(0xffffffffu, mx, off));
            }
            if (lane == 0) {
                if (isrec)                    P_rec  = v;
                else if (ble1)                { /* mask: unused */ }
                else if (mn >= 0 && mx <= 9)  P_feat = v;
                else if (mn >= 1 && mx <= 16) { /* charlen: unused */ }
                else                          P_word = v;
            }
        } else if (w == 5) {
            for (int j = 0; j < fp.n50; j++) {
                const float* f = fp.c50[j];
                bool nz = false;
                for (int k = lane; k < 50; k += 32) nz |= (f[k] != 0.0f);
                bool anynz = __any_sync(0xffffffffu, nz);
                if (lane == 0) { if (anynz) P_femb = f; else P_cb = f; }
            }
        } else if (w == 6 && lane == 0) {
            P_wemb = fp.wemb; P_cemb = fp.cemb; P_cw = fp.cw;
            P_pw = fp.pw; P_pb = fp.pb; P_tr = fp.tr;
            P_wihf = fp.wihf; P_wihb = fp.wihb;
            P_whhf = fp.whhf; P_whhb = fp.whhb;
            P_bf = fp.bf; P_bb = fp.bb;
            P_char = fp.chr; P_len = fp.len;
        }
    } else if (bid <= GT*KT) {
        __shared__ float tile[32][33];
        int t  = bid - 1;
        int kt = t / GT;
        int gt = t % GT;
        int tx  = tid & 31;
        int ty0 = tid >> 5;
        #pragma unroll
        for (int h2 = 0; h2 < 2; h2++) {
            int ty = ty0 + h2*16;
            int g2 = gt*32 + ty;
            int k  = kt*32 + tx;
            float v = 0.f;
            if (k < INN && g2 < N2)
                v = (g2 < G4) ? fp.wihf[g2*INN + k] : fp.wihb[(g2-G4)*INN + k];
            tile[ty][tx] = v;
        }
        __syncthreads();
        #pragma unroll
        for (int h2 = 0; h2 < 2; h2++) {
            int r  = ty0 + h2*16;
            int k2 = kt*32 + r;
            int g2 = gt*32 + tx;
            if (k2 < KP)
                g_W[(size_t)k2*N2P + g2] = tile[tx][r];
        }
    } else {
        const float* char_emb = fp.cemb;
        const float* conv_w   = fp.cw;
        __shared__ float sce[CDD];
        int c = bid - (GT*KT + 1);
        for (int d = tid; d < CDD; d += blockDim.x)
            sce[d] = char_emb[c*CDD + d];
        __syncthreads();
        if (tid < 3*CHH) {
            int k = tid / CHH, o = tid % CHH;
            float acc = 0.f;
            #pragma unroll 4
            for (int d = 0; d < CDD; d++)
                acc += __ldg(conv_w + (o*CDD + d)*3 + k) * sce[d];
            g_proj[(c*3 + k)*CHH + o] = acc;
        }
    }
}

// ---------------- K1: char conv + max-pool ----------------
__global__ void k_charmax() {
    const int*   batch_char = P_char;
    const float* conv_b     = P_cb;
    __shared__ int chs[4][CLL];
    int t = threadIdx.x & 63;
    int ns = threadIdx.x >> 6;
    int n = blockIdx.x*4 + ns;
    if (t < CLL) chs[ns][t] = batch_char[n*CLL + t];
    __syncthreads();
    if (t < CHH) {
        float bo = conv_b[t];
        float best = -1e30f;
        #pragma unroll
        for (int p = 0; p < CLL; p++) {
            float v = bo;
            #pragma unroll
            for (int k = 0; k < 3; k++) {
                int q = p + k - 1;
                if (q >= 0 && q < CLL)
                    v += __ldg(&g_proj[(chs[ns][q]*3 + k)*CHH + t]);
            }
            best = fmaxf(best, v);
        }
        g_charmax[n*CHH + t] = best;
    }
}

// ---------------- K2: SGEMM — A stored as duplicated pairs (no fdup in inner loop) ----------------
#define BM 128
#define BN 128
#define BKK 8
#define NT (KP/BKK)   // 45
__global__ __launch_bounds__(256, 2)
void k_gemm() {
    const float* b_f  = P_bf;
    const float* b_b  = P_bb;
    const float* femb = P_femb;
    // As entries are pre-duplicated (a,a) pairs -> FFMA2 operand straight from LDS.128
    __shared__ __align__(16) ull   As[2][BKK][BM];
    __shared__ __align__(16) float Bs[2][BKK][BN];
    __shared__ int sw[BM], sr[BM], sf[BM];
    int bm = blockIdx.x * BM;
    int bn = blockIdx.y * BN;
    int tid = threadIdx.x;
    int am = tid >> 1, ak = (tid & 1) * 4;
    int bk = tid >> 5, bn4 = (tid & 31) * 4;
    int tx = tid & 15, ty = tid >> 4;

    for (int i = tid; i < BM; i += 256) {
        int m = bm + i;
        sw[i] = P_word[m];
        sr[i] = P_rec[m];
        sf[i] = P_feat[m];
    }
    __syncthreads();
    int myr = sr[am], myf = sf[am];
    const float* wrow = P_wemb + (size_t)sw[am]*WDD;

    ull acc2[8][4];
    #pragma unroll
    for (int i = 0; i < 8; i++)
        #pragma unroll
        for (int j = 0; j < 4; j++) acc2[i][j] = 0ull;

    float4 a4, b4;
    #define GATHER(t) {                                                          \
        int k = (t)*BKK + ak;                                                    \
        if (k + 3 < WDD) {                                                       \
            a4 = *(const float4*)(wrow + k);                                     \
        } else {                                                                 \
            float vv[4];                                                         \
            _Pragma("unroll")                                                    \
            for (int c = 0; c < 4; c++) {                                        \
                int kk2 = k + c;                                                 \
                float x = 0.f;                                                   \
                if (kk2 < WDD)           x = __ldg(wrow + kk2);                  \
                else if (kk2 < WDD+CHH)  x = g_charmax[myr*CHH + kk2 - WDD];     \
                else if (kk2 < INN)      x = __ldg(femb + myf*FDD + (kk2 - WDD - CHH)); \
                vv[c] = x;                                                       \
            }                                                                    \
            a4 = make_float4(vv[0], vv[1], vv[2], vv[3]);                        \
        }                                                                        \
        b4 = *(const float4*)(g_W + (size_t)((t)*BKK + bk)*N2P + bn + bn4);      \
    }
    #define STORE(buf) {                                                         \
        As[buf][ak+0][am] = fdup(a4.x); As[buf][ak+1][am] = fdup(a4.y);          \
        As[buf][ak+2][am] = fdup(a4.z); As[buf][ak+3][am] = fdup(a4.w);          \
        *(float4*)&Bs[buf][bk][bn4] = b4;                                        \
    }

    GATHER(0); STORE(0);
    __syncthreads();
    for (int t = 0; t < NT; t++) {
        int cur = t & 1;
        if (t + 1 < NT) GATHER(t + 1);
        #pragma unroll
        for (int kk = 0; kk < BKK; kk++) {
            ulonglong2 aP0 = *(const ulonglong2*)&As[cur][kk][ty*8];
            ulonglong2 aP1 = *(const ulonglong2*)&As[cur][kk][ty*8 + 2];
            ulonglong2 aP2 = *(const ulonglong2*)&As[cur][kk][ty*8 + 4];
            ulonglong2 aP3 = *(const ulonglong2*)&As[cur][kk][ty*8 + 6];
            ulonglong2 bL = *(const ulonglong2*)&Bs[cur][kk][tx*4];
            ulonglong2 bH = *(const ulonglong2*)&Bs[cur][kk][64 + tx*4];
            ull br2[4];
            br2[0] = bL.x; br2[1] = bL.y; br2[2] = bH.x; br2[3] = bH.y;
            ull a2[8];
            a2[0] = aP0.x; a2[1] = aP0.y; a2[2] = aP1.x; a2[3] = aP1.y;
            a2[4] = aP2.x; a2[5] = aP2.y; a2[6] = aP3.x; a2[7] = aP3.y;
            #pragma unroll
            for (int i = 0; i < 8; i++) {
                #pragma unroll
                for (int j2 = 0; j2 < 4; j2++)
                    acc2[i][j2] = ffma2(a2[i], br2[j2], acc2[i][j2]);
            }
        }
        if (t + 1 < NT) STORE(cur ^ 1);
        __syncthreads();
    }

    #pragma unroll
    for (int i = 0; i < 8; i++) {
        int m = bm + ty*8 + i;
        #pragma unroll
        for (int j2 = 0; j2 < 4; j2++) {
            float2 v = fupk(acc2[i][j2]);
            int col = (j2 < 2) ? (tx*4 + 2*j2) : (64 + tx*4 + 2*(j2-2));
            int n0 = bn + col;
            if (n0 < N2) {
                float bias0 = (n0 < G4) ? __ldg(b_f + n0) : __ldg(b_b + n0 - G4);
                g_pre[(size_t)m*N2 + n0] = v.x + bias0;
            }
            int n1 = n0 + 1;
            if (n1 < N2) {
                float bias1 = (n1 < G4) ? __ldg(b_f + n1) : __ldg(b_b + n1 - G4);
                g_pre[(size_t)m*N2 + n1] = v.y + bias1;
            }
        }
    }
}

// ---------------- K3: LSTM recurrence — R11/R13 version (best known: 170us) ----------------
__global__ __launch_bounds__(416, 1)
void k_lstm() {
    int bx  = blockIdx.x;
    int dir = bx >> 6;
    int b   = bx & 63;
    const float* w = (dir == 0) ? P_whhf : P_whhb;
    int tid  = threadIdx.x;
    int lane = tid & 31;
    int q    = lane >> 3;
    int j    = (tid >> 5)*8 + (lane & 7);   // 0..103 (warp 12 partial)
    bool jok = (j < HH);

    __shared__ __align__(16) ull h_dup[2][104];   // 4 chunks x 26 (25 used + pad)

    ull wif[25], wgo[25];
    {
        int k0 = q*25;
        if (jok) {
            const float* wi = w + (size_t)j*HH        + k0;
            const float* wf = w + (size_t)(HH+j)*HH   + k0;
            const float* wg = w + (size_t)(2*HH+j)*HH + k0;
            const float* wo = w + (size_t)(3*HH+j)*HH + k0;
            #pragma unroll
            for (int t = 0; t < 25; t++) {
                wif[t] = fpk(__ldg(wi + t), __ldg(wf + t));
                wgo[t] = fpk(__ldg(wg + t), __ldg(wo + t));
            }
        } else {
            #pragma unroll
            for (int t = 0; t < 25; t++) { wif[t] = 0ull; wgo[t] = 0ull; }
        }
    }
    if (tid < 104) { h_dup[0][tid] = 0ull; h_dup[1][tid] = 0ull; }
    float c = 0.f, h = 0.f;
    int len = P_len[b];
    int hidx = (j/25)*26 + (j%25);
    __syncthreads();

    const float* preb = g_pre + (size_t)(b*SS)*N2 + dir*G4 + q*HH + j;
    int s0 = dir ? (SS-1) : 0;
    int ds = dir ? -1 : 1;

    #define CLAMPS(x) ((x) < 0 ? 0 : ((x) > SS-1 ? SS-1 : (x)))
    float p0 = jok ? __ldg(preb + (size_t)CLAMPS(s0)*N2)        : 0.f;
    float p1 = jok ? __ldg(preb + (size_t)CLAMPS(s0+ds)*N2)     : 0.f;
    float p2 = jok ? __ldg(preb + (size_t)CLAMPS(s0+2*ds)*N2)   : 0.f;

    int s = s0;
    for (int it = 0; it < SS; it++, s += ds) {
        int s3 = CLAMPS(s + 3*ds);
        float pnew = jok ? __ldg(preb + (size_t)s3*N2) : 0.f;

        int cur = it & 1;
        ull aif = (q == 0) ? fpk(p0, 0.f) : (q == 1) ? fpk(0.f, p0) : 0ull;
        ull ago = (q == 2) ? fpk(p0, 0.f) : (q == 3) ? fpk(0.f, p0) : 0ull;
        const ulonglong2* hd2 = (const ulonglong2*)&h_dup[cur][q*26];
        #pragma unroll
        for (int t = 0; t < 12; t++) {
            ulonglong2 hp = hd2[t];
            aif = ffma2(wif[2*t],   hp.x, aif);
            ago = ffma2(wgo[2*t],   hp.x, ago);
            aif = ffma2(wif[2*t+1], hp.y, aif);
            ago = ffma2(wgo[2*t+1], hp.y, ago);
        }
        {
            ull hp = h_dup[cur][q*26 + 24];
            aif = ffma2(wif[24], hp, aif);
            ago = ffma2(wgo[24], hp, ago);
        }
        aif = faddx2(aif, __shfl_xor_sync(0xffffffffu, aif, 8));
        ago = faddx2(ago, __shfl_xor_sync(0xffffffffu, ago, 8));
        aif = faddx2(aif, __shfl_xor_sync(0xffffffffu, aif, 16));
        ago = faddx2(ago, __shfl_xor_sync(0xffffffffu, ago, 16));
        float2 sif = fupk(aif);
        float2 sgo = fupk(ago);
        float cn = sigf(sif.y)*c + sigf(sif.x)*tanhf_fast(sgo.x);
        float hn = sigf(sgo.y)*tanhf_fast(cn);
        if (s < len) { c = cn; h = hn; }
        if (q == 0 && jok) {
            h_dup[cur ^ 1][hidx] = fdup(h);
            g_lstm[(size_t)(b*SS + s)*(2*HH) + dir*HH + j] = h;
        }
        __syncthreads();
        p0 = p1; p1 = p2; p2 = pnew;
    }
    #undef CLAMPS
}

// ---------------- K4: emission projection (4 accumulator chains) ----------------
__global__ void k_feats() {
    const float* proj_w = P_pw;
    const float* proj_b = P_pb;
    __shared__ float rows[8][2*HH];
    int wrp = threadIdx.x >> 5;
    int lane = threadIdx.x & 31;
    int n = blockIdx.x*8 + wrp;
    const float* src = g_lstm + (size_t)n*(2*HH);
    for (int k = lane; k < 2*HH; k += 32)
        rows[wrp][k] = src[k];
    __syncwarp();
    if (lane < TT) {
        float a0 = 0.f, a1 = 0.f, a2 = 0.f, a3 = 0.f;
        #pragma unroll 4
        for (int k = 0; k < 2*HH; k += 4) {
            a0 += rows[wrp][k+0] * __ldg(proj_w + (k+0)*TT + lane);
            a1 += rows[wrp][k+1] * __ldg(proj_w + (k+1)*TT + lane);
            a2 += rows[wrp][k+2] * __ldg(proj_w + (k+2)*TT + lane);
            a3 += rows[wrp][k+3] * __ldg(proj_w + (k+3)*TT + lane);
        }
        g_feats[(size_t)n*TT + lane] = __ldg(proj_b + lane) + ((a0 + a1) + (a2 + a3));
    }
}

// ---------------- K5: Viterbi — tree argmax ----------------
__device__ __forceinline__ void argmax22(const float* sc, float& bv, int& bi) {
    float v[22]; int ix[22];
    #pragma unroll
    for (int i = 0; i < 22; i++) { v[i] = sc[i]; ix[i] = i; }
    #pragma unroll
    for (int st = 16; st >= 1; st >>= 1) {
        #pragma unroll
        for (int i = 0; i < 22; i++) {
            if (i < st && i + st < 22) {
                bool r = v[i + st] > v[i];
                v[i]  = r ? v[i + st]  : v[i];
                ix[i] = r ? ix[i + st] : ix[i];
            }
        }
    }
    bv = v[0]; bi = ix[0];
}

__global__ void k_viterbi(float* __restrict__ out) {
    const float* trans = P_tr;
    const int*   lens  = P_len;
    int b = blockIdx.x;
    int j = threadIdx.x;
    __shared__ float tr[TT*TT];
    __shared__ float delta[TT];
    __shared__ unsigned char bp[(SS-1)*TT];
    for (int i = j; i < TT*TT; i += 32) tr[i] = trans[i];
    int len = lens[b];
    const float* fb = g_feats + (size_t)b*SS*TT;
    __syncwarp();
    if (j < TT) delta[j] = tr[START_TAG*TT + j] + __ldg(fb + j);
    __syncwarp();

    float fcur = (j < TT) ? __ldg(fb + TT + j) : 0.f;
    for (int t = 1; t < SS; t++) {
        float fnext = 0.f;
        if (j < TT && t < SS-1) fnext = __ldg(fb + (size_t)(t+1)*TT + j);
        float nd = 0.f; int nb = 0;
        if (j < TT) {
            float sc[TT];
            #pragma unroll
            for (int i = 0; i < TT; i++) sc[i] = delta[i] + tr[i*TT + j];
            float best; int bi;
            argmax22(sc, best, bi);
            if (t < len) { nd = best + fcur; nb = bi; }
            else         { nd = delta[j];    nb = j;  }
        }
        __syncwarp();
        if (j < TT) { delta[j] = nd; bp[(t-1)*TT + j] = (unsigned char)nb; }
        __syncwarp();
        fcur = fnext;
    }
    if (j == 0) {
        float sc[TT];
        #pragma unroll
        for (int i = 0; i < TT; i++) sc[i] = delta[i] + tr[i*TT + STOP_TAG];
        float best; int bi;
        argmax22(sc, best, bi);
        int tag = bi;
        out[b*SS + SS-1] = (float)tag;
        for (int s = SS-2; s >= 0; s--) {
            tag = bp[s*TT + tag];
            out[b*SS + s] = (float)tag;
        }
    }
}

// ---------------- launcher ----------------
extern "C" void kernel_launch(void* const* d_in, const int* in_sizes, int n_in,
                              void* d_out, int out_size) {
    FixedPtrs fp;
    fp.n16 = 0; fp.n50 = 0;
    int n142 = 0, n40k = 0, n400 = 0;
    for (int i = 0; i < n_in; i++) {
        int s = in_sizes[i];
        const void* p = d_in[i];
        if (s == 15000000)      fp.wemb = (const float*)p;
        else if (s == 256000)   fp.chr  = (const int*)p;
        else if (s == 64)       fp.len  = (const int*)p;
        else if (s == 30000)    fp.cemb = (const float*)p;
        else if (s == 45000)    fp.cw   = (const float*)p;
        else if (s == 4400)     fp.pw   = (const float*)p;
        else if (s == 22)       fp.pb   = (const float*)p;
        else if (s == 484)      fp.tr   = (const float*)p;
        else if (s == 142000) { if (n142++ == 0) fp.wihf = (const float*)p; else fp.wihb = (const float*)p; }
        else if (s == 40000)  { if (n40k++ == 0) fp.whhf = (const float*)p; else fp.whhb = (const float*)p; }
        else if (s == 400)    { if (n400++ == 0) fp.bf   = (const float*)p; else fp.bb   = (const float*)p; }
        else if (s == 50)     { if (fp.n50 < 2) fp.c50[fp.n50++] = (const float*)p; }
        else if (s == 16000)  { if (fp.n16 < 5) fp.c16[fp.n16++] = (const int*)p; }
    }

    k_init<<<1 + GT*KT + CVV, 512>>>(fp);    // launch 0
    k_charmax<<<NS/4, 256>>>();              // launch 1
    dim3 gg((NS + BM - 1)/BM, (N2P + BN - 1)/BN);
    k_gemm<<<gg, 256>>>();                   // launch 2
    k_lstm<<<128, 416>>>();                  // launch 3  <- ncu target (control: ~170us)
    k_feats<<<NS/8, 256>>>();                // launch 4
    k_viterbi<<<BB, 32>>>((float*)d_out);    // launch 5
}

// round 16
// speedup vs baseline: 1.2890x; 1.0741x over previous
#include <cuda_runtime.h>
#include <math.h>

// ---------------- problem constants ----------------
#define BB   64
#define SS   250
#define CLL  16
#define CVV  100
#define CHH  50
#define FDD  5
#define WDD  300
#define CDD  300
#define HH   100
#define G4   400      // 4*H
#define INN  355      // WD + CH + FD
#define KP   360      // padded K for GEMM
#define N2   800      // both directions' gates
#define N2P  896      // padded N for GEMM loads
#define NS   (BB*SS)  // 16000
#define TT   22
#define START_TAG 20
#define STOP_TAG  21

typedef unsigned long long ull;

// ---------------- resolved input pointers ----------------
__device__ const int   *P_word, *P_feat, *P_len, *P_char, *P_rec;
__device__ const float *P_cemb, *P_wemb, *P_femb, *P_cw, *P_cb;
__device__ const float *P_wihf, *P_whhf, *P_bf, *P_wihb, *P_whhb, *P_bb;
__device__ const float *P_pw, *P_pb, *P_tr;

// ---------------- scratch ----------------
__device__ float g_proj[CVV*3*CHH];
__device__ float g_charmax[NS*CHH];
__device__ float g_W[KP*N2P];
__device__ float g_pre[NS*N2];
__device__ float g_lstm[NS*(2*HH)];
__device__ float g_feats[NS*TT];

// MUFU-based activations (R11 formulas; rel_err 0.0)
__device__ __forceinline__ float sigf(float x) {
    return __fdividef(1.0f, 1.0f + __expf(-x));
}
__device__ __forceinline__ float tanhf_fast(float x) {
    float e = __expf(2.0f * x);
    return 1.0f - __fdividef(2.0f, e + 1.0f);
}

// ---------------- packed fp32x2 helpers ----------------
__device__ __forceinline__ ull ffma2(ull a, ull b, ull c) {
    ull d;
    asm("fma.rn.f32x2 %0, %1, %2, %3;" : "=l"(d) : "l"(a), "l"(b), "l"(c));
    return d;
}
__device__ __forceinline__ ull faddx2(ull a, ull b) {
    ull d;
    asm("add.rn.f32x2 %0, %1, %2;" : "=l"(d) : "l"(a), "l"(b));
    return d;
}
__device__ __forceinline__ ull fdup(float a) {
    ull r;
    asm("mov.b64 %0, {%1, %1};" : "=l"(r) : "f"(a));
    return r;
}
__device__ __forceinline__ ull fpk(float a, float b) {
    ull r;
    asm("mov.b64 %0, {%1, %2};" : "=l"(r) : "f"(a), "f"(b));
    return r;
}
__device__ __forceinline__ float2 fupk(ull v) {
    float2 f;
    asm("mov.b64 {%0, %1}, %2;" : "=f"(f.x), "=f"(f.y) : "l"(v));
    return f;
}

// ---------------- host-resolved fixed pointers ----------------
struct FixedPtrs {
    const float *wemb, *cemb, *cw, *pw, *pb, *tr;
    const float *wihf, *wihb, *whhf, *whhb, *bf, *bb;
    const int   *chr, *len;
    const int   *c16[5]; int n16;
    const float *c50[2]; int n50;
};

// ---------------- K0: fused resolve + coalesced buildW transpose + charproj ----------------
#define GT 28   // g2 tiles (28*32 = 896 = N2P)
#define KT 12   // k  tiles (12*32 = 384 >= KP)
__global__ __launch_bounds__(512, 2)
void k_init(FixedPtrs fp) {
    int bid = blockIdx.x;
    int tid = threadIdx.x;
    if (bid == 0) {
        int w = tid >> 5, lane = tid & 31;
        if (w < fp.n16 && w < 5) {
            const int* v = fp.c16[w];
            bool isrec = true, ble1 = true;
            int mn = 0x7fffffff, mx = -0x7fffffff;
            #pragma unroll
            for (int k = lane; k < 256; k += 32) {
                int x = v[k];
                if (x != k) isrec = false;
                unsigned u = (unsigned)x;
                if (((u)&0xFFu) > 1u || ((u>>8)&0xFFu) > 1u ||
                    ((u>>16)&0xFFu) > 1u || ((u>>24)&0xFFu) > 1u) ble1 = false;
                mn = min(mn, x); mx = max(mx, x);
            }
            isrec = __all_sync(0xffffffffu, isrec);
            ble1  = __all_sync(0xffffffffu, ble1);
            #pragma unroll
            for (int off = 16; off; off >>= 1) {
                mn = min(mn, __shfl_xor_sync(0xffffffffu, mn, off));
                mx = max(mx, __shfl_xor_sync(0xffffffffu, mx, off));
            }
            if (lane == 0) {
                if (isrec)                    P_rec  = v;
                else if (ble1)                { /* mask: unused */ }
                else if (mn >= 0 && mx <= 9)  P_feat = v;
                else if (mn >= 1 && mx <= 16) { /* charlen: unused */ }
                else                          P_word = v;
            }
        } else if (w == 5) {
            for (int j = 0; j < fp.n50; j++) {
                const float* f = fp.c50[j];
                bool nz = false;
                for (int k = lane; k < 50; k += 32) nz |= (f[k] != 0.0f);
                bool anynz = __any_sync(0xffffffffu, nz);
                if (lane == 0) { if (anynz) P_femb = f; else P_cb = f; }
            }
        } else if (w == 6 && lane == 0) {
            P_wemb = fp.wemb; P_cemb = fp.cemb; P_cw = fp.cw;
            P_pw = fp.pw; P_pb = fp.pb; P_tr = fp.tr;
            P_wihf = fp.wihf; P_wihb = fp.wihb;
            P_whhf = fp.whhf; P_whhb = fp.whhb;
            P_bf = fp.bf; P_bb = fp.bb;
            P_char = fp.chr; P_len = fp.len;
        }
    } else if (bid <= GT*KT) {
        __shared__ float tile[32][33];
        int t  = bid - 1;
        int kt = t / GT;
        int gt = t % GT;
        int tx  = tid & 31;
        int ty0 = tid >> 5;
        #pragma unroll
        for (int h2 = 0; h2 < 2; h2++) {
            int ty = ty0 + h2*16;
            int g2 = gt*32 + ty;
            int k  = kt*32 + tx;
            float v = 0.f;
            if (k < INN && g2 < N2)
                v = (g2 < G4) ? fp.wihf[g2*INN + k] : fp.wihb[(g2-G4)*INN + k];
            tile[ty][tx] = v;
        }
        __syncthreads();
        #pragma unroll
        for (int h2 = 0; h2 < 2; h2++) {
            int r  = ty0 + h2*16;
            int k2 = kt*32 + r;
            int g2 = gt*32 + tx;
            if (k2 < KP)
                g_W[(size_t)k2*N2P + g2] = tile[tx][r];
        }
    } else {
        const float* char_emb = fp.cemb;
        const float* conv_w   = fp.cw;
        __shared__ float sce[CDD];
        int c = bid - (GT*KT + 1);
        for (int d = tid; d < CDD; d += blockDim.x)
            sce[d] = char_emb[c*CDD + d];
        __syncthreads();
        if (tid < 3*CHH) {
            int k = tid / CHH, o = tid % CHH;
            float acc = 0.f;
            #pragma unroll 4
            for (int d = 0; d < CDD; d++)
                acc += __ldg(conv_w + (o*CDD + d)*3 + k) * sce[d];
            g_proj[(c*3 + k)*CHH + o] = acc;
        }
    }
}

// ---------------- K1: char conv + max-pool ----------------
__global__ void k_charmax() {
    const int*   batch_char = P_char;
    const float* conv_b     = P_cb;
    __shared__ int chs[4][CLL];
    int t = threadIdx.x & 63;
    int ns = threadIdx.x >> 6;
    int n = blockIdx.x*4 + ns;
    if (t < CLL) chs[ns][t] = batch_char[n*CLL + t];
    __syncthreads();
    if (t < CHH) {
        float bo = conv_b[t];
        float best = -1e30f;
        #pragma unroll
        for (int p = 0; p < CLL; p++) {
            float v = bo;
            #pragma unroll
            for (int k = 0; k < 3; k++) {
                int q = p + k - 1;
                if (q >= 0 && q < CLL)
                    v += __ldg(&g_proj[(chs[ns][q]*3 + k)*CHH + t]);
            }
            best = fmaxf(best, v);
        }
        g_charmax[n*CHH + t] = best;
    }
}

// ---------------- K2: SGEMM (R13 version, 213us) ----------------
#define BM 128
#define BN 128
#define BKK 8
#define NT (KP/BKK)   // 45
__global__ __launch_bounds__(256, 2)
void k_gemm() {
    const float* b_f  = P_bf;
    const float* b_b  = P_bb;
    const float* femb = P_femb;
    __shared__ __align__(16) float As[2][BKK][BM + 4];
    __shared__ __align__(16) float Bs[2][BKK][BN];
    __shared__ int sw[BM], sr[BM], sf[BM];
    int bm = blockIdx.x * BM;
    int bn = blockIdx.y * BN;
    int tid = threadIdx.x;
    int am = tid >> 1, ak = (tid & 1) * 4;
    int bk = tid >> 5, bn4 = (tid & 31) * 4;
    int tx = tid & 15, ty = tid >> 4;

    for (int i = tid; i < BM; i += 256) {
        int m = bm + i;
        sw[i] = P_word[m];
        sr[i] = P_rec[m];
        sf[i] = P_feat[m];
    }
    __syncthreads();
    int myr = sr[am], myf = sf[am];
    const float* wrow = P_wemb + (size_t)sw[am]*WDD;

    ull acc2[8][4];
    #pragma unroll
    for (int i = 0; i < 8; i++)
        #pragma unroll
        for (int j = 0; j < 4; j++) acc2[i][j] = 0ull;

    float4 a4, b4;
    #define GATHER(t) {                                                          \
        int k = (t)*BKK + ak;                                                    \
        if (k + 3 < WDD) {                                                       \
            a4 = *(const float4*)(wrow + k);                                     \
        } else {                                                                 \
            float vv[4];                                                         \
            _Pragma("unroll")                                                    \
            for (int c = 0; c < 4; c++) {                                        \
                int kk2 = k + c;                                                 \
                float x = 0.f;                                                   \
                if (kk2 < WDD)           x = __ldg(wrow + kk2);                  \
                else if (kk2 < WDD+CHH)  x = g_charmax[myr*CHH + kk2 - WDD];     \
                else if (kk2 < INN)      x = __ldg(femb + myf*FDD + (kk2 - WDD - CHH)); \
                vv[c] = x;                                                       \
            }                                                                    \
            a4 = make_float4(vv[0], vv[1], vv[2], vv[3]);                        \
        }                                                                        \
        b4 = *(const float4*)(g_W + (size_t)((t)*BKK + bk)*N2P + bn + bn4);      \
    }
    #define STORE(buf) {                                                         \
        As[buf][ak+0][am] = a4.x; As[buf][ak+1][am] = a4.y;                      \
        As[buf][ak+2][am] = a4.z; As[buf][ak+3][am] = a4.w;                      \
        *(float4*)&Bs[buf][bk][bn4] = b4;                                        \
    }

    GATHER(0); STORE(0);
    __syncthreads();
    for (int t = 0; t < NT; t++) {
        int cur = t & 1;
        if (t + 1 < NT) GATHER(t + 1);
        #pragma unroll
        for (int kk = 0; kk < BKK; kk++) {
            float4 a0 = *(const float4*)&As[cur][kk][ty*8];
            float4 a1 = *(const float4*)&As[cur][kk][ty*8 + 4];
            ulonglong2 bL = *(const ulonglong2*)&Bs[cur][kk][tx*4];
            ulonglong2 bH = *(const ulonglong2*)&Bs[cur][kk][64 + tx*4];
            ull br2[4];
            br2[0] = bL.x; br2[1] = bL.y; br2[2] = bH.x; br2[3] = bH.y;
            float ar[8];
            ar[0]=a0.x; ar[1]=a0.y; ar[2]=a0.z; ar[3]=a0.w;
            ar[4]=a1.x; ar[5]=a1.y; ar[6]=a1.z; ar[7]=a1.w;
            #pragma unroll
            for (int i = 0; i < 8; i++) {
                ull a2 = fdup(ar[i]);
                #pragma unroll
                for (int j2 = 0; j2 < 4; j2++)
                    acc2[i][j2] = ffma2(a2, br2[j2], acc2[i][j2]);
            }
        }
        if (t + 1 < NT) STORE(cur ^ 1);
        __syncthreads();
    }

    #pragma unroll
    for (int i = 0; i < 8; i++) {
        int m = bm + ty*8 + i;
        #pragma unroll
        for (int j2 = 0; j2 < 4; j2++) {
            float2 v = fupk(acc2[i][j2]);
            int col = (j2 < 2) ? (tx*4 + 2*j2) : (64 + tx*4 + 2*(j2-2));
            int n0 = bn + col;
            if (n0 < N2) {
                float bias0 = (n0 < G4) ? __ldg(b_f + n0) : __ldg(b_b + n0 - G4);
                g_pre[(size_t)m*N2 + n0] = v.x + bias0;
            }
            int n1 = n0 + 1;
            if (n1 < N2) {
                float bias1 = (n1 < G4) ? __ldg(b_f + n1) : __ldg(b_b + n1 - G4);
                g_pre[(size_t)m*N2 + n1] = v.y + bias1;
            }
        }
    }
}

// ---------------- K3: LSTM recurrence — R11/R13 version (170us) ----------------
__global__ __launch_bounds__(416, 1)
void k_lstm() {
    int bx  = blockIdx.x;
    int dir = bx >> 6;
    int b   = bx & 63;
    const float* w = (dir == 0) ? P_whhf : P_whhb;
    int tid  = threadIdx.x;
    int lane = tid & 31;
    int q    = lane >> 3;
    int j    = (tid >> 5)*8 + (lane & 7);   // 0..103 (warp 12 partial)
    bool jok = (j < HH);

    __shared__ __align__(16) ull h_dup[2][104];   // 4 chunks x 26 (25 used + pad)

    ull wif[25], wgo[25];
    {
        int k0 = q*25;
        if (jok) {
            const float* wi = w + (size_t)j*HH        + k0;
            const float* wf = w + (size_t)(HH+j)*HH   + k0;
            const float* wg = w + (size_t)(2*HH+j)*HH + k0;
            const float* wo = w + (size_t)(3*HH+j)*HH + k0;
            #pragma unroll
            for (int t = 0; t < 25; t++) {
                wif[t] = fpk(__ldg(wi + t), __ldg(wf + t));
                wgo[t] = fpk(__ldg(wg + t), __ldg(wo + t));
            }
        } else {
            #pragma unroll
            for (int t = 0; t < 25; t++) { wif[t] = 0ull; wgo[t] = 0ull; }
        }
    }
    if (tid < 104) { h_dup[0][tid] = 0ull; h_dup[1][tid] = 0ull; }
    float c = 0.f, h = 0.f;
    int len = P_len[b];
    int hidx = (j/25)*26 + (j%25);
    __syncthreads();

    const float* preb = g_pre + (size_t)(b*SS)*N2 + dir*G4 + q*HH + j;
    int s0 = dir ? (SS-1) : 0;
    int ds = dir ? -1 : 1;

    #define CLAMPS(x) ((x) < 0 ? 0 : ((x) > SS-1 ? SS-1 : (x)))
    float p0 = jok ? __ldg(preb + (size_t)CLAMPS(s0)*N2)        : 0.f;
    float p1 = jok ? __ldg(preb + (size_t)CLAMPS(s0+ds)*N2)     : 0.f;
    float p2 = jok ? __ldg(preb + (size_t)CLAMPS(s0+2*ds)*N2)   : 0.f;

    int s = s0;
    for (int it = 0; it < SS; it++, s += ds) {
        int s3 = CLAMPS(s + 3*ds);
        float pnew = jok ? __ldg(preb + (size_t)s3*N2) : 0.f;

        int cur = it & 1;
        ull aif = (q == 0) ? fpk(p0, 0.f) : (q == 1) ? fpk(0.f, p0) : 0ull;
        ull ago = (q == 2) ? fpk(p0, 0.f) : (q == 3) ? fpk(0.f, p0) : 0ull;
        const ulonglong2* hd2 = (const ulonglong2*)&h_dup[cur][q*26];
        #pragma unroll
        for (int t = 0; t < 12; t++) {
            ulonglong2 hp = hd2[t];
            aif = ffma2(wif[2*t],   hp.x, aif);
            ago = ffma2(wgo[2*t],   hp.x, ago);
            aif = ffma2(wif[2*t+1], hp.y, aif);
            ago = ffma2(wgo[2*t+1], hp.y, ago);
        }
        {
            ull hp = h_dup[cur][q*26 + 24];
            aif = ffma2(wif[24], hp, aif);
            ago = ffma2(wgo[24], hp, ago);
        }
        aif = faddx2(aif, __shfl_xor_sync(0xffffffffu, aif, 8));
        ago = faddx2(ago, __shfl_xor_sync(0xffffffffu, ago, 8));
        aif = faddx2(aif, __shfl_xor_sync(0xffffffffu, aif, 16));
        ago = faddx2(ago, __shfl_xor_sync(0xffffffffu, ago, 16));
        float2 sif = fupk(aif);
        float2 sgo = fupk(ago);
        float cn = sigf(sif.y)*c + sigf(sif.x)*tanhf_fast(sgo.x);
        float hn = sigf(sgo.y)*tanhf_fast(cn);
        if (s < len) { c = cn; h = hn; }
        if (q == 0 && jok) {
            h_dup[cur ^ 1][hidx] = fdup(h);
            g_lstm[(size_t)(b*SS + s)*(2*HH) + dir*HH + j] = h;
        }
        __syncthreads();
        p0 = p1; p1 = p2; p2 = pnew;
    }
    #undef CLAMPS
}

// ---------------- K4: emission projection (4 accumulator chains) ----------------
__global__ void k_feats() {
    const float* proj_w = P_pw;
    const float* proj_b = P_pb;
    __shared__ float rows[8][2*HH];
    int wrp = threadIdx.x >> 5;
    int lane = threadIdx.x & 31;
    int n = blockIdx.x*8 + wrp;
    const float* src = g_lstm + (size_t)n*(2*HH);
    for (int k = lane; k < 2*HH; k += 32)
        rows[wrp][k] = src[k];
    __syncwarp();
    if (lane < TT) {
        float a0 = 0.f, a1 = 0.f, a2 = 0.f, a3 = 0.f;
        #pragma unroll 4
        for (int k = 0; k < 2*HH; k += 4) {
            a0 += rows[wrp][k+0] * __ldg(proj_w + (k+0)*TT + lane);
            a1 += rows[wrp][k+1] * __ldg(proj_w + (k+1)*TT + lane);
            a2 += rows[wrp][k+2] * __ldg(proj_w + (k+2)*TT + lane);
            a3 += rows[wrp][k+3] * __ldg(proj_w + (k+3)*TT + lane);
        }
        g_feats[(size_t)n*TT + lane] = __ldg(proj_b + lane) + ((a0 + a1) + (a2 + a3));
    }
}

// ---------------- K5: Viterbi — register-resident delta via shfl broadcast ----------------
// lane j (<22) holds delta[j]; per step all lanes obtain every delta[i] via
// broadcast shfl. No smem delta, no __syncwarp in the loop (shfl orders).
// Tie-break (first max) preserved by the same strict-'>' tree.
__device__ __forceinline__ void argmax22(const float* sc, float& bv, int& bi) {
    float v[22]; int ix[22];
    #pragma unroll
    for (int i = 0; i < 22; i++) { v[i] = sc[i]; ix[i] = i; }
    #pragma unroll
    for (int st = 16; st >= 1; st >>= 1) {
        #pragma unroll
        for (int i = 0; i < 22; i++) {
            if (i < st && i + st < 22) {
                bool r = v[i + st] > v[i];
                v[i]  = r ? v[i + st]  : v[i];
                ix[i] = r ? ix[i + st] : ix[i];
            }
        }
    }
    bv = v[0]; bi = ix[0];
}

__global__ void k_viterbi(float* __restrict__ out) {
    const float* trans = P_tr;
    const int*   lens  = P_len;
    int b = blockIdx.x;
    int j = threadIdx.x;
    __shared__ float tr[TT*TT];
    __shared__ unsigned char bp[(SS-1)*TT];
    for (int i = j; i < TT*TT; i += 32) tr[i] = trans[i];
    int len = lens[b];
    const float* fb = g_feats + (size_t)b*SS*TT;
    __syncwarp();

    // trj[i] = tr[i*TT + j] cached in registers for this lane's column
    float trj[TT];
    #pragma unroll
    for (int i = 0; i < TT; i++) trj[i] = tr[i*TT + j % TT];

    float dj = (j < TT) ? tr[START_TAG*TT + j] + __ldg(fb + j) : -1e30f;

    float fcur = (j < TT) ? __ldg(fb + TT + j) : 0.f;
    for (int t = 1; t < SS; t++) {
        float fnext = 0.f;
        if (j < TT && t < SS-1) fnext = __ldg(fb + (size_t)(t+1)*TT + j);
        // broadcast all deltas (lanes 0..21 are sources; all lanes execute)
        float sc[TT];
        #pragma unroll
        for (int i = 0; i < TT; i++) {
            float di = __shfl_sync(0xffffffffu, dj, i);
            sc[i] = di + trj[i];
        }
        float best; int bi;
        argmax22(sc, best, bi);
        float nd; int nb;
        if (t < len) { nd = best + fcur; nb = bi; }
        else         { nd = dj;          nb = j;  }
        dj = nd;
        if (j < TT) bp[(t-1)*TT + j] = (unsigned char)nb;
        fcur = fnext;
    }
    // final: delta[i] + tr[i][STOP], argmax on every lane (identical result)
    float sc[TT];
    #pragma unroll
    for (int i = 0; i < TT; i++) {
        float di = __shfl_sync(0xffffffffu, dj, i);
        sc[i] = di + tr[i*TT + STOP_TAG];
    }
    float best; int bi;
    argmax22(sc, best, bi);
    __syncwarp();
    if (j == 0) {
        int tag = bi;
        out[b*SS + SS-1] = (float)tag;
        for (int s = SS-2; s >= 0; s--) {
            tag = bp[s*TT + tag];
            out[b*SS + s] = (float)tag;
        }
    }
}

// ---------------- launcher ----------------
extern "C" void kernel_launch(void* const* d_in, const int* in_sizes, int n_in,
                              void* d_out, int out_size) {
    FixedPtrs fp;
    fp.n16 = 0; fp.n50 = 0;
    int n142 = 0, n40k = 0, n400 = 0;
    for (int i = 0; i < n_in; i++) {
        int s = in_sizes[i];
        const void* p = d_in[i];
        if (s == 15000000)      fp.wemb = (const float*)p;
        else if (s == 256000)   fp.chr  = (const int*)p;
        else if (s == 64)       fp.len  = (const int*)p;
        else if (s == 30000)    fp.cemb = (const float*)p;
        else if (s == 45000)    fp.cw   = (const float*)p;
        else if (s == 4400)     fp.pw   = (const float*)p;
        else if (s == 22)       fp.pb   = (const float*)p;
        else if (s == 484)      fp.tr   = (const float*)p;
        else if (s == 142000) { if (n142++ == 0) fp.wihf = (const float*)p; else fp.wihb = (const float*)p; }
        else if (s == 40000)  { if (n40k++ == 0) fp.whhf = (const float*)p; else fp.whhb = (const float*)p; }
        else if (s == 400)    { if (n400++ == 0) fp.bf   = (const float*)p; else fp.bb   = (const float*)p; }
        else if (s == 50)     { if (fp.n50 < 2) fp.c50[fp.n50++] = (const float*)p; }
        else if (s == 16000)  { if (fp.n16 < 5) fp.c16[fp.n16++] = (const int*)p; }
    }

    k_init<<<1 + GT*KT + CVV, 512>>>(fp);    // launch 0
    k_charmax<<<NS/4, 256>>>();              // launch 1
    dim3 gg((NS + BM - 1)/BM, (N2P + BN - 1)/BN);
    k_gemm<<<gg, 256>>>();                   // launch 2
    k_lstm<<<128, 416>>>();                  // launch 3  <- ncu target
    k_feats<<<NS/8, 256>>>();                // launch 4
    k_viterbi<<<BB, 32>>>((float*)d_out);    // launch 5
}